// round 4
// baseline (speedup 1.0000x reference)
#include <cuda_runtime.h>
#include <cstdint>

#define H   128
#define XD  64
#define ED  16
#define NMAX 50000
#define EMAX 640000
#define GPMAX 512
#define BN_EPS 1e-5f

// ---------------- scratch (static device globals; no allocation) ----------------
__device__ __align__(16) float g_h  [(size_t)NMAX * H];
__device__ __align__(16) float g_t  [(size_t)NMAX * H];
__device__ __align__(16) float g_h1 [(size_t)NMAX * H];
__device__ __align__(16) float g_pooled[GPMAX * H];
__device__ __align__(16) float g_colsum[H];
__device__ __align__(16) float g_colsumsq[H];
__device__ __align__(16) float g_scale[H];
__device__ __align__(16) float g_shift[H];

// ---------------- helpers ----------------
__device__ __forceinline__ void red_add_v4(float* addr, float4 v) {
    asm volatile("red.global.add.v4.f32 [%0], {%1,%2,%3,%4};"
                 :: "l"(addr), "f"(v.x), "f"(v.y), "f"(v.z), "f"(v.w)
                 : "memory");
}

// ---------------- generic tiled SGEMM: C[M,128] = op(A[M,K]) @ W[K,128] + bias ----
// BN_IN:  apply y = relu(a*scale[k]+shift[k]) to A elements at load time
// STATS:  accumulate per-column sum / sumsq of (acc+bias) into gsum/gsq
// RELU_OUT: relu on output
template<int K, bool BN_IN, bool RELU_OUT, bool STATS>
__global__ void __launch_bounds__(256) gemm_k(
    const float* __restrict__ A, const float* __restrict__ W,
    const float* __restrict__ bias, float* __restrict__ C, int M,
    const float* __restrict__ bscale, const float* __restrict__ bshift,
    float* __restrict__ gsum, float* __restrict__ gsq)
{
    constexpr int NT = K / 8;
    __shared__ __align__(16) float As[2][8][132];
    __shared__ __align__(16) float Bs[2][8][128];
    __shared__ float s_sum[128];
    __shared__ float s_sq[128];

    const int tid = threadIdx.x;
    const int tx  = tid & 15;        // 16 col-groups of 8
    const int ty  = tid >> 4;        // 16 row-groups of 8
    const int rowBlk = blockIdx.x * 128;

    if (STATS && tid < 128) { s_sum[tid] = 0.f; s_sq[tid] = 0.f; }

    const int aRow = tid >> 1;             // 0..127
    const int aK   = (tid & 1) << 2;       // 0 or 4
    const int wK   = tid >> 5;             // 0..7
    const int wN   = (tid & 31) << 2;      // 0..124

    float acc[8][8];
    #pragma unroll
    for (int r = 0; r < 8; r++)
        #pragma unroll
        for (int c = 0; c < 8; c++) acc[r][c] = 0.f;

    float4 va, vb;
    // ---- prologue: tile 0 ----
    {
        int grow = rowBlk + aRow;
        if (grow < M) {
            va = *(const float4*)(A + (size_t)grow * K + aK);
            if (BN_IN) {
                int kb = aK;
                va.x = fmaxf(va.x * __ldg(bscale + kb + 0) + __ldg(bshift + kb + 0), 0.f);
                va.y = fmaxf(va.y * __ldg(bscale + kb + 1) + __ldg(bshift + kb + 1), 0.f);
                va.z = fmaxf(va.z * __ldg(bscale + kb + 2) + __ldg(bshift + kb + 2), 0.f);
                va.w = fmaxf(va.w * __ldg(bscale + kb + 3) + __ldg(bshift + kb + 3), 0.f);
            }
        } else va = make_float4(0.f, 0.f, 0.f, 0.f);
        vb = *(const float4*)(W + (size_t)wK * 128 + wN);
    }
    As[0][aK + 0][aRow] = va.x;
    As[0][aK + 1][aRow] = va.y;
    As[0][aK + 2][aRow] = va.z;
    As[0][aK + 3][aRow] = va.w;
    *(float4*)&Bs[0][wK][wN] = vb;
    __syncthreads();

    for (int kt = 0; kt < NT; kt++) {
        const int cur = kt & 1;
        if (kt + 1 < NT) {
            int gk = (kt + 1) * 8;
            int grow = rowBlk + aRow;
            if (grow < M) {
                va = *(const float4*)(A + (size_t)grow * K + gk + aK);
                if (BN_IN) {
                    int kb = gk + aK;
                    va.x = fmaxf(va.x * __ldg(bscale + kb + 0) + __ldg(bshift + kb + 0), 0.f);
                    va.y = fmaxf(va.y * __ldg(bscale + kb + 1) + __ldg(bshift + kb + 1), 0.f);
                    va.z = fmaxf(va.z * __ldg(bscale + kb + 2) + __ldg(bshift + kb + 2), 0.f);
                    va.w = fmaxf(va.w * __ldg(bscale + kb + 3) + __ldg(bshift + kb + 3), 0.f);
                }
            } else va = make_float4(0.f, 0.f, 0.f, 0.f);
            vb = *(const float4*)(W + (size_t)(gk + wK) * 128 + wN);
        }
        #pragma unroll
        for (int kk = 0; kk < 8; kk++) {
            float4 a0 = *(const float4*)&As[cur][kk][ty * 8];
            float4 a1 = *(const float4*)&As[cur][kk][ty * 8 + 4];
            float4 b0 = *(const float4*)&Bs[cur][kk][tx * 8];
            float4 b1 = *(const float4*)&Bs[cur][kk][tx * 8 + 4];
            float a[8] = {a0.x, a0.y, a0.z, a0.w, a1.x, a1.y, a1.z, a1.w};
            float b[8] = {b0.x, b0.y, b0.z, b0.w, b1.x, b1.y, b1.z, b1.w};
            #pragma unroll
            for (int r = 0; r < 8; r++)
                #pragma unroll
                for (int c = 0; c < 8; c++)
                    acc[r][c] += a[r] * b[c];
        }
        if (kt + 1 < NT) {
            const int nxt = cur ^ 1;
            As[nxt][aK + 0][aRow] = va.x;
            As[nxt][aK + 1][aRow] = va.y;
            As[nxt][aK + 2][aRow] = va.z;
            As[nxt][aK + 3][aRow] = va.w;
            *(float4*)&Bs[nxt][wK][wN] = vb;
        }
        __syncthreads();
    }

    // ---- epilogue ----
    float bias_c[8];
    #pragma unroll
    for (int j = 0; j < 8; j++) bias_c[j] = __ldg(bias + tx * 8 + j);

    float ps[8], pq[8];
    if (STATS) {
        #pragma unroll
        for (int j = 0; j < 8; j++) { ps[j] = 0.f; pq[j] = 0.f; }
    }

    #pragma unroll
    for (int r = 0; r < 8; r++) {
        int grow = rowBlk + ty * 8 + r;
        if (grow < M) {
            float o[8];
            #pragma unroll
            for (int j = 0; j < 8; j++) {
                float v = acc[r][j] + bias_c[j];
                if (STATS) { ps[j] += v; pq[j] += v * v; }
                if (RELU_OUT) v = fmaxf(v, 0.f);
                o[j] = v;
            }
            *(float4*)(C + (size_t)grow * 128 + tx * 8)     = make_float4(o[0], o[1], o[2], o[3]);
            *(float4*)(C + (size_t)grow * 128 + tx * 8 + 4) = make_float4(o[4], o[5], o[6], o[7]);
        }
    }

    if (STATS) {
        #pragma unroll
        for (int j = 0; j < 8; j++) {
            atomicAdd(&s_sum[tx * 8 + j], ps[j]);
            atomicAdd(&s_sq [tx * 8 + j], pq[j]);
        }
        __syncthreads();
        if (tid < 128) {
            atomicAdd(gsum + tid, s_sum[tid]);
            atomicAdd(gsq  + tid, s_sq[tid]);
        }
    }
}

// ---------------- t = h  (and zero BN stat accumulators) ----------------
__global__ void copy_t_kernel(const float* __restrict__ h, float* __restrict__ t,
                              int n4, float* __restrict__ cs, float* __restrict__ cq)
{
    if (blockIdx.x == 0 && threadIdx.x < 128) { cs[threadIdx.x] = 0.f; cq[threadIdx.x] = 0.f; }
    int i = blockIdx.x * blockDim.x + threadIdx.x;
    int stride = gridDim.x * blockDim.x;
    for (; i < n4; i += stride)
        ((float4*)t)[i] = ((const float4*)h)[i];
}

// ---------------- message passing: t[dst] += relu(h[src] + edge_attr@Ew + Eb) ----
// one warp per edge; lane handles 4 features; e recomputed on the fly
// NOTE: edge_index is int32 (JAX x64 disabled downcasts int64 -> int32)
__global__ void __launch_bounds__(256) msg_kernel(
    const float* __restrict__ h, float* __restrict__ t,
    const float* __restrict__ ea, const float* __restrict__ eW,
    const float* __restrict__ eb, const int* __restrict__ ei, int E)
{
    __shared__ __align__(16) float Ws[ED * H];
    __shared__ __align__(16) float ebs[H];
    for (int i = threadIdx.x; i < ED * H; i += blockDim.x) Ws[i] = eW[i];
    if (threadIdx.x < H) ebs[threadIdx.x] = eb[threadIdx.x];
    __syncthreads();

    const int lane = threadIdx.x & 31;
    const int f = lane * 4;
    int warp = (blockIdx.x * blockDim.x + threadIdx.x) >> 5;
    const int nwarps = (gridDim.x * blockDim.x) >> 5;
    const float4 bias4 = *(const float4*)(ebs + f);

    for (int e = warp; e < E; e += nwarps) {
        int src = __ldg(ei + e);
        int dst = __ldg(ei + E + e);
        const float4* ap = (const float4*)(ea + (size_t)e * ED);
        float4 q0 = __ldg(ap + 0);
        float4 q1 = __ldg(ap + 1);
        float4 q2 = __ldg(ap + 2);
        float4 q3 = __ldg(ap + 3);
        float4 acc = bias4;
        float4 w;
        #define EK(a_, k_) \
            w = *(const float4*)(Ws + (k_) * H + f); \
            acc.x += (a_) * w.x; acc.y += (a_) * w.y; \
            acc.z += (a_) * w.z; acc.w += (a_) * w.w;
        EK(q0.x, 0)  EK(q0.y, 1)  EK(q0.z, 2)  EK(q0.w, 3)
        EK(q1.x, 4)  EK(q1.y, 5)  EK(q1.z, 6)  EK(q1.w, 7)
        EK(q2.x, 8)  EK(q2.y, 9)  EK(q2.z, 10) EK(q2.w, 11)
        EK(q3.x, 12) EK(q3.y, 13) EK(q3.z, 14) EK(q3.w, 15)
        #undef EK
        float4 hv = *(const float4*)(h + (size_t)src * H + f);
        float4 m;
        m.x = fmaxf(hv.x + acc.x, 0.f);
        m.y = fmaxf(hv.y + acc.y, 0.f);
        m.z = fmaxf(hv.z + acc.z, 0.f);
        m.w = fmaxf(hv.w + acc.w, 0.f);
        red_add_v4(t + (size_t)dst * H + f, m);
    }
}

// ---------------- BN finalize: scale/shift per column ----------------
__global__ void bn_finalize_kernel(const float* __restrict__ cs, const float* __restrict__ cq,
                                   const float* __restrict__ g, const float* __restrict__ b,
                                   int N, float* __restrict__ scale, float* __restrict__ shift)
{
    int j = threadIdx.x;
    float invN = 1.f / (float)N;
    float mean = cs[j] * invN;
    float var  = cq[j] * invN - mean * mean;
    float inv  = rsqrtf(var + BN_EPS);
    float sc   = g[j] * inv;
    scale[j] = sc;
    shift[j] = b[j] - mean * sc;
}

// ---------------- zero (float4) ----------------
__global__ void zero4_kernel(float* __restrict__ p, int n4)
{
    int i = blockIdx.x * blockDim.x + threadIdx.x;
    int stride = gridDim.x * blockDim.x;
    for (; i < n4; i += stride)
        ((float4*)p)[i] = make_float4(0.f, 0.f, 0.f, 0.f);
}

// ---------------- global add pool (batch is sorted -> run-length local reduce) ----
// NOTE: batch is int32
__global__ void __launch_bounds__(256) pool_kernel(
    const float* __restrict__ h, const int* __restrict__ batch,
    float* __restrict__ pooled, int N)
{
    const int lane = threadIdx.x & 31;
    const int warp = (blockIdx.x * blockDim.x + threadIdx.x) >> 5;
    const int CHUNK = 64;
    int n0 = warp * CHUNK;
    if (n0 >= N) return;
    int n1 = n0 + CHUNK; if (n1 > N) n1 = N;
    const int f = lane * 4;

    int cur = __ldg(batch + n0);
    float4 acc = make_float4(0.f, 0.f, 0.f, 0.f);
    for (int n = n0; n < n1; n++) {
        int b = __ldg(batch + n);
        if (b != cur) {
            red_add_v4(pooled + (size_t)cur * H + f, acc);
            acc = make_float4(0.f, 0.f, 0.f, 0.f);
            cur = b;
        }
        float4 v = *(const float4*)(h + (size_t)n * H + f);
        acc.x += v.x; acc.y += v.y; acc.z += v.z; acc.w += v.w;
    }
    red_add_v4(pooled + (size_t)cur * H + f, acc);
}

// ---------------- final FC: out[G,10] = pooled @ fc_w + fc_b ----------------
__global__ void final_gemm_kernel(const float* __restrict__ pooled,
                                  const float* __restrict__ fcw, const float* __restrict__ fcb,
                                  float* __restrict__ out, int G)
{
    __shared__ float row[H];
    int g = blockIdx.x;
    row[threadIdx.x] = pooled[(size_t)g * H + threadIdx.x];
    __syncthreads();
    if (threadIdx.x < 10) {
        float acc = fcb[threadIdx.x];
        #pragma unroll 8
        for (int k = 0; k < H; k++)
            acc += row[k] * fcw[k * 10 + threadIdx.x];
        out[g * 10 + threadIdx.x] = acc;
    }
}

// ---------------- launch ----------------
extern "C" void kernel_launch(void* const* d_in, const int* in_sizes, int n_in,
                              void* d_out, int out_size)
{
    const float* x      = (const float*)d_in[0];
    const float* ea     = (const float*)d_in[1];
    const float* node_w = (const float*)d_in[2];
    const float* node_b = (const float*)d_in[3];
    const float* edge_w = (const float*)d_in[4];
    const float* edge_b = (const float*)d_in[5];
    const float* lin1_w = (const float*)d_in[6];
    const float* lin1_b = (const float*)d_in[7];
    const float* bn_g   = (const float*)d_in[8];
    const float* bn_b   = (const float*)d_in[9];
    const float* lin2_w = (const float*)d_in[10];
    const float* lin2_b = (const float*)d_in[11];
    const float* fc_w   = (const float*)d_in[12];
    const float* fc_b   = (const float*)d_in[13];
    const int* ei       = (const int*)d_in[14];
    const int* batch    = (const int*)d_in[15];

    const int N = in_sizes[0] / XD;
    const int E = in_sizes[1] / ED;
    const int G = out_size / 10;

    float *hP, *tP, *h1P, *plP, *csP, *cqP, *scP, *shP;
    cudaGetSymbolAddress((void**)&hP,  g_h);
    cudaGetSymbolAddress((void**)&tP,  g_t);
    cudaGetSymbolAddress((void**)&h1P, g_h1);
    cudaGetSymbolAddress((void**)&plP, g_pooled);
    cudaGetSymbolAddress((void**)&csP, g_colsum);
    cudaGetSymbolAddress((void**)&cqP, g_colsumsq);
    cudaGetSymbolAddress((void**)&scP, g_scale);
    cudaGetSymbolAddress((void**)&shP, g_shift);

    const int gemmGrid = (N + 127) / 128;

    // node encoder: h = x @ node_w + node_b
    gemm_k<XD, false, false, false><<<gemmGrid, 256>>>(
        x, node_w, node_b, hP, N, nullptr, nullptr, nullptr, nullptr);

    for (int l = 0; l < 3; l++) {
        // t = h; zero BN stats
        copy_t_kernel<<<2048, 256>>>(hP, tP, N * H / 4, csP, cqP);
        // t[dst] += relu(h[src] + e)   (e recomputed on the fly)
        msg_kernel<<<2368, 256>>>(hP, tP, ea, edge_w, edge_b, ei, E);
        // h1 = t @ W1 + b1, with column sum/sumsq accumulation
        gemm_k<H, false, false, true><<<gemmGrid, 256>>>(
            tP, lin1_w + (size_t)l * H * H, lin1_b + l * H, h1P, N,
            nullptr, nullptr, csP, cqP);
        // BN scale/shift
        bn_finalize_kernel<<<1, H>>>(csP, cqP, bn_g + l * H, bn_b + l * H, N, scP, shP);
        // h = relu( relu(bn(h1)) @ W2 + b2 )
        gemm_k<H, true, true, false><<<gemmGrid, 256>>>(
            h1P, lin2_w + (size_t)l * H * H, lin2_b + l * H, hP, N,
            scP, shP, nullptr, nullptr);
    }

    // pooled = segment_sum(h, batch)
    zero4_kernel<<<(G * H / 4 + 255) / 256, 256>>>(plP, G * H / 4);
    int poolWarps = (N + 63) / 64;
    pool_kernel<<<(poolWarps + 7) / 8, 256>>>(hP, batch, plP, N);

    // out = pooled @ fc_w + fc_b
    final_gemm_kernel<<<G, H>>>(plP, fc_w, fc_b, (float*)d_out, G);
}